// round 13
// baseline (speedup 1.0000x reference)
#include <cuda_runtime.h>
#include <math.h>
#include <stdint.h>

#define T_   6400
#define Dm   512
#define Nn   2048
#define NBUCK 128
#define INV_N (1.0f / 2048.0f)

// offsets = [0, 2048, 3584, 4608, 6400]; lengths all multiples of 64.
__constant__ int c_off[5] = {0, 2048, 3584, 4608, 6400};

__device__ float g_xn[(size_t)T_ * Dm];
__device__ float g_uvqkrT[(size_t)1024 * Dm];   // uvqk transposed [n][k], tf32-rounded
__device__ float g_owr[(size_t)Dm * 256];       // o_w tf32-rounded [n][k]
__device__ float g_h[(size_t)T_ * 1024];
__device__ float g_vT[(size_t)256 * T_];        // V transposed: [feature][token]
__device__ float g_attn[(size_t)T_ * 256];
__device__ float g_oin[(size_t)T_ * 256];

// ---- tf32 / mma / cp.async helpers ----------------------------------------
__device__ __forceinline__ float tf32r(float x) {
    float y; asm("cvt.rna.tf32.f32 %0, %1;" : "=f"(y) : "f"(x)); return y;
}
__device__ __forceinline__ float4 tf32r4(float4 v) {
    v.x = tf32r(v.x); v.y = tf32r(v.y); v.z = tf32r(v.z); v.w = tf32r(v.w);
    return v;
}
__device__ __forceinline__ float tanh_hw(float x) {
    float y; asm("tanh.approx.f32 %0, %1;" : "=f"(y) : "f"(x)); return y;
}
__device__ __forceinline__ void mma8(float* c, const float* a, const float* b) {
    asm volatile(
        "mma.sync.aligned.m16n8k8.row.col.f32.tf32.tf32.f32 "
        "{%0,%1,%2,%3},{%4,%5,%6,%7},{%8,%9},{%0,%1,%2,%3};"
        : "+f"(c[0]), "+f"(c[1]), "+f"(c[2]), "+f"(c[3])
        : "r"(__float_as_uint(a[0])), "r"(__float_as_uint(a[1])),
          "r"(__float_as_uint(a[2])), "r"(__float_as_uint(a[3])),
          "r"(__float_as_uint(b[0])), "r"(__float_as_uint(b[1])));
}
__device__ __forceinline__ void cpa16(void* dst, const void* src) {
    uint32_t d = (uint32_t)__cvta_generic_to_shared(dst);
    asm volatile("cp.async.cg.shared.global [%0], [%1], 16;" :: "r"(d), "l"(src));
}
__device__ __forceinline__ void cpa_commit() { asm volatile("cp.async.commit_group;"); }
__device__ __forceinline__ void cpa_wait0()  { asm volatile("cp.async.wait_group 0;"); }

// ---------------------------------------------------------------------------
// uvqk transpose + tf32 round: [512][1024] -> [1024][512]
// ---------------------------------------------------------------------------
__global__ __launch_bounds__(256) void cvtT_kernel(const float* __restrict__ in,
                                                   float* __restrict__ out) {
    __shared__ float tile[32][33];
    int bx = blockIdx.x * 32;  // n
    int by = blockIdx.y * 32;  // k
    int tx = threadIdx.x & 31, ty = threadIdx.x >> 5;
#pragma unroll
    for (int r = 0; r < 4; r++)
        tile[ty + 8 * r][tx] = in[(size_t)(by + ty + 8 * r) * 1024 + bx + tx];
    __syncthreads();
#pragma unroll
    for (int r = 0; r < 4; r++)
        out[(size_t)(bx + ty + 8 * r) * Dm + by + tx] = tf32r(tile[tx][ty + 8 * r]);
}

// ---------------------------------------------------------------------------
// tf32 pre-round (o_w)
// ---------------------------------------------------------------------------
__global__ __launch_bounds__(256) void cvt_tf32_kernel(const float4* __restrict__ in,
                                                       float4* __restrict__ out) {
    int i = blockIdx.x * 256 + threadIdx.x;
    out[i] = tf32r4(in[i]);
}

// ---------------------------------------------------------------------------
// LayerNorm over D=512, warp-per-row, tf32-rounded output
// ---------------------------------------------------------------------------
__global__ __launch_bounds__(256) void ln_x_kernel(const float* __restrict__ x,
                                                   float* __restrict__ xn) {
    int row = blockIdx.x * 8 + (threadIdx.x >> 5);
    int lane = threadIdx.x & 31;
    const float* r = x + (size_t)row * Dm;
    float4 v[4];
    float s = 0.f, q = 0.f;
#pragma unroll
    for (int i = 0; i < 4; i++) {
        v[i] = *reinterpret_cast<const float4*>(&r[lane * 4 + i * 128]);
        s += v[i].x + v[i].y + v[i].z + v[i].w;
        q += v[i].x * v[i].x + v[i].y * v[i].y + v[i].z * v[i].z + v[i].w * v[i].w;
    }
#pragma unroll
    for (int o = 16; o > 0; o >>= 1) {
        s += __shfl_xor_sync(0xffffffffu, s, o);
        q += __shfl_xor_sync(0xffffffffu, q, o);
    }
    float m = s * (1.f / Dm);
    float rstd = rsqrtf(q * (1.f / Dm) - m * m + 1e-6f);
    float* ov = xn + (size_t)row * Dm;
#pragma unroll
    for (int i = 0; i < 4; i++) {
        float4 w;
        w.x = tf32r((v[i].x - m) * rstd); w.y = tf32r((v[i].y - m) * rstd);
        w.z = tf32r((v[i].z - m) * rstd); w.w = tf32r((v[i].w - m) * rstd);
        *reinterpret_cast<float4*>(&ov[lane * 4 + i * 128]) = w;
    }
}

// ---------------------------------------------------------------------------
// h = silu(xn @ uvqk)  tf32 MMA, 128x64 tile, BK=32, cp.async double buffer.
// B read from transposed uvqkrT [n][k] -> sB[n][72]; k-relabel: MMA slot pair
// (t,t+4) reads physical k (2t,2t+1) -> all fragment loads are LDS.64.
// Epilogue: u natural -> h; v TRANSPOSED -> g_vT; q/k alpha-permuted -> h.
// ---------------------------------------------------------------------------
#define G1_SMEM (18432 * 4)

__global__ __launch_bounds__(256) void gemm_silu_kernel(const float* __restrict__ A,
                                                        const float* __restrict__ BmT,
                                                        float* __restrict__ C,
                                                        float* __restrict__ vT) {
    extern __shared__ float sm[];
    float* sA = sm;            // [2][128][36]  A[m][k]
    float* sB = sm + 9216;     // [2][64][72]   B[n][k]
    int bm = blockIdx.y * 128, bn = blockIdx.x * 64;
    int tid = threadIdx.x, lane = tid & 31, wid = tid >> 5;
    int g = lane >> 2, t = lane & 3;
    int wm = (wid >> 1) * 32, wn = (wid & 1) * 32;

    auto pf = [&](int k0, int buf) {
        float* dA = sA + buf * 4608;
        float* dB = sB + buf * 4608;
#pragma unroll
        for (int p = 0; p < 4; p++) {
            int idx = tid + p * 256;
            int row = idx >> 3, f4 = (idx & 7) << 2;
            cpa16(&dA[row * 36 + f4], &A[(size_t)(bm + row) * Dm + k0 + f4]);
        }
#pragma unroll
        for (int p = 0; p < 2; p++) {
            int idx = tid + p * 256;
            int row = idx >> 3, f4 = (idx & 7) << 2;
            cpa16(&dB[row * 72 + f4], &BmT[(size_t)(bn + row) * Dm + k0 + f4]);
        }
        cpa_commit();
    };

    float acc[2][4][4] = {};
    pf(0, 0);
    for (int it = 0; it < 16; it++) {
        cpa_wait0();
        __syncthreads();
        if (it + 1 < 16) pf((it + 1) * 32, (it + 1) & 1);
        float* cA = sA + (it & 1) * 4608;
        float* cB = sB + (it & 1) * 4608;
#pragma unroll
        for (int kk = 0; kk < 32; kk += 8) {
            float a[2][4], bb[4][2];
#pragma unroll
            for (int i = 0; i < 2; i++) {
                int r = wm + 16 * i + g;
                float2 f0 = *reinterpret_cast<const float2*>(&cA[r * 36 + kk + 2 * t]);
                float2 f1 = *reinterpret_cast<const float2*>(&cA[(r + 8) * 36 + kk + 2 * t]);
                a[i][0] = f0.x; a[i][1] = f1.x; a[i][2] = f0.y; a[i][3] = f1.y;
            }
#pragma unroll
            for (int j = 0; j < 4; j++) {
                float2 fb = *reinterpret_cast<const float2*>(
                    &cB[(wn + 8 * j + g) * 72 + kk + 2 * t]);
                bb[j][0] = fb.x; bb[j][1] = fb.y;
            }
#pragma unroll
            for (int i = 0; i < 2; i++)
#pragma unroll
                for (int j = 0; j < 4; j++) mma8(acc[i][j], a[i], bb[j]);
        }
        __syncthreads();
    }
    int sec = bn >> 8;                    // 0: u, 1: v, >=2: q/k
    int p0 = (t < 2) ? 4 * t : 4 * t - 7; // alpha perm for q/k
#pragma unroll
    for (int i = 0; i < 2; i++) {
        int r = bm + wm + 16 * i + g;
#pragma unroll
        for (int j = 0; j < 4; j++) {
            float* s = acc[i][j];
            float e0 = tf32r(__fdividef(s[0], 1.f + __expf(-s[0])));
            float e1 = tf32r(__fdividef(s[1], 1.f + __expf(-s[1])));
            float e2 = tf32r(__fdividef(s[2], 1.f + __expf(-s[2])));
            float e3 = tf32r(__fdividef(s[3], 1.f + __expf(-s[3])));
            if (sec == 0) {
                int c = bn + wn + 8 * j + 2 * t;
                *reinterpret_cast<float2*>(&C[(size_t)r * 1024 + c]) = make_float2(e0, e1);
                *reinterpret_cast<float2*>(&C[(size_t)(r + 8) * 1024 + c]) = make_float2(e2, e3);
            } else if (sec == 1) {
                int f = (bn - 256) + wn + 8 * j + 2 * t;   // 0..255
                vT[(size_t)f * T_ + r] = e0;
                vT[(size_t)(f + 1) * T_ + r] = e1;
                vT[(size_t)f * T_ + r + 8] = e2;
                vT[(size_t)(f + 1) * T_ + r + 8] = e3;
            } else {
                int cb = bn + wn + 8 * j;
                C[(size_t)r * 1024 + cb + p0] = e0;
                C[(size_t)r * 1024 + cb + p0 + 2] = e1;
                C[(size_t)(r + 8) * 1024 + cb + p0] = e2;
                C[(size_t)(r + 8) * 1024 + cb + p0 + 2] = e3;
            }
        }
    }
}

// ---------------------------------------------------------------------------
// Split-K jagged causal attention, 75KB smem -> 3 CTAs/SM.
// Q staged via V buf1 then register-hoisted; S overwrites consumed K tile.
// ---------------------------------------------------------------------------
#define ATTN_SMEM (18796 * 4)

__global__ __launch_bounds__(256, 3) void attn_kernel(const float* __restrict__ h,
                                                      const float* __restrict__ vT,
                                                      const int* __restrict__ ts,
                                                      const float* __restrict__ ts_w,
                                                      float* __restrict__ attn) {
    // decode unit -> (b, tile, chunk); chunks(t) = (t>>3)+1, tiles descending
    int u = blockIdx.x;
    int b;
    if (u < 80) { b = 0; }
    else if (u < 128) { b = 1; u -= 80; }
    else if (u < 152) { b = 2; u -= 128; }
    else { b = 3; u -= 152; }
    int base = c_off[b];
    int Tb = (c_off[b + 1] - base) >> 6;
    int tile = 0, chunk = 0;
    for (int tt = Tb - 1; tt >= 0; --tt) {
        int c = (tt >> 3) + 1;
        if (u < c) { tile = tt; chunk = u; break; }
        u -= c;
    }
    int head = blockIdx.y;
    int q0 = tile * 64;
    int kt0 = chunk * 8;
    int nkt = min(kt0 + 8, tile + 1) - kt0;

    extern __shared__ float sm[];
    float* sKb = sm;                // [2][64][72]  K tiles; S scratch after QK
    float* sVT = sm + 9216;         // [2][64][72]  V^T tiles; buf1 stages Q first
    float* sW  = sm + 18432;        // 129
    int* sTq = (int*)(sm + 18561);  // 64
    int* sTk = (int*)(sm + 18625);  // [2][64]
    float2* sET = (float2*)(sm + 18754);  // 21 x {k0, e^(k0+1)}, 8B aligned

    int tid = threadIdx.x;
    int hofQ = 512 + head * 64, hofK = 768 + head * 64;
    const float* vTh = vT + (size_t)head * 64 * T_;

    auto pfKV = [&](int kt, int buf) {
        int k0 = kt * 64;
        if (tid < 64) sTk[buf * 64 + tid] = ts[b * Nn + k0 + tid];
        float* dK = sKb + buf * 4608;
        float* dV = sVT + buf * 4608;
#pragma unroll
        for (int p = 0; p < 4; p++) {
            int l = tid + p * 256;
            int row = l >> 4, f4 = (l & 15) << 2;
            cpa16(&dK[row * 72 + f4],
                  &h[(size_t)(base + k0 + row) * 1024 + hofK + f4]);
            cpa16(&dV[row * 72 + f4],
                  &vTh[(size_t)row * T_ + base + k0 + f4]);
        }
    };

    if (tid < 129) sW[tid] = ts_w[tid];
    if (tid < 64) sTq[tid] = ts[b * Nn + q0 + tid];
    if (tid >= 160 && tid < 181) {  // bucket table init
        int e = tid - 160;
        int k0 = (int)((float)e * 0.69314718f);
        sET[e] = make_float2((float)k0, expf((float)(k0 + 1)));
    }
    // Q staged into V buf1 region
    float* dQ = sVT + 4608;
#pragma unroll
    for (int p = 0; p < 4; p++) {
        int l = tid + p * 256;
        int row = l >> 4, f4 = (l & 15) << 2;
        cpa16(&dQ[row * 72 + f4], &h[(size_t)(base + q0 + row) * 1024 + hofQ + f4]);
    }
    pfKV(kt0, 0);
    cpa_commit();

    int lane = tid & 31, wid = tid >> 5;
    int g = lane >> 2, t = lane & 3;
    int m0 = (wid >> 1) * 16, n0 = (wid & 1) * 32;
    int mgrp = wid >> 1;
    float o[4][4] = {};

    cpa_wait0();
    __syncthreads();

    // hoist Q fragments (q-section alpha-permuted: pair (t,t+4) adjacent)
    float qf[8][4];
#pragma unroll
    for (int ks = 0; ks < 8; ks++) {
        float2 f0 = *reinterpret_cast<const float2*>(&dQ[(m0 + g) * 72 + ks * 8 + 2 * t]);
        float2 f1 = *reinterpret_cast<const float2*>(&dQ[(m0 + g + 8) * 72 + ks * 8 + 2 * t]);
        qf[ks][0] = f0.x; qf[ks][1] = f1.x; qf[ks][2] = f0.y; qf[ks][3] = f1.y;
    }
    __syncthreads();  // Q hoisted everywhere before buf1 gets prefetched over

    for (int ii = 0; ii < nkt; ii++) {
        int kt = kt0 + ii;
        int buf = ii & 1;
        if (ii + 1 < nkt) { pfKV(kt + 1, buf ^ 1); cpa_commit(); }

        float* sK = sKb + buf * 4608;   // K now, S after the mid barrier
        float* sV = sVT + buf * 4608;
        int* sTkb = sTk + buf * 64;

        // ---- S = Q K^T ----
        float s4[4][4] = {};
#pragma unroll
        for (int ks = 0; ks < 8; ks++) {
#pragma unroll
            for (int j = 0; j < 4; j++) {
                float2 kb = *reinterpret_cast<const float2*>(
                    &sK[(n0 + 8 * j + g) * 72 + ks * 8 + 2 * t]);
                float bb[2] = {kb.x, kb.y};
                mma8(s4[j], qf[ks], bb);
            }
        }
        __syncthreads();  // all warps done reading K; sK becomes S storage

        // ---- score: bias (exp-bit bucket) + silu (HW tanh) + /N; mask on diag ----
        int tq0 = sTq[m0 + g], tq1 = sTq[m0 + g + 8];
        bool diag = (kt == tile);
#pragma unroll
        for (int j = 0; j < 4; j++) {
            int col = n0 + 8 * j + 2 * t;
            int tk0 = sTkb[col], tk1 = sTkb[col + 1];
            float r[4];
            int tqs[4] = {tq0, tq0, tq1, tq1};
            int tks[4] = {tk0, tk1, tk0, tk1};
#pragma unroll
            for (int e = 0; e < 4; e++) {
                float w = fabsf((float)(tqs[e] - tks[e])) + 1.0f;
                int ex = (int)(__float_as_uint(w) >> 23) - 127;
                float2 et = sET[ex];
                int bk = (int)et.x + (w >= et.y ? 1 : 0);
                float z = s4[j][e] + sW[bk];
                float sig = fmaf(0.5f, tanh_hw(0.5f * z), 0.5f);
                r[e] = z * sig * INV_N;
            }
            if (diag) {
                int qg0 = m0 + g, qg1 = qg0 + 8;
                if (col > qg0) r[0] = 0.f;
                if (col + 1 > qg0) r[1] = 0.f;
                if (col > qg1) r[2] = 0.f;
                if (col + 1 > qg1) r[3] = 0.f;
            }
            *reinterpret_cast<float2*>(&sK[(m0 + g) * 72 + col]) =
                make_float2(tf32r(r[0]), tf32r(r[1]));
            *reinterpret_cast<float2*>(&sK[(m0 + g + 8) * 72 + col]) =
                make_float2(tf32r(r[2]), tf32r(r[3]));
        }
        // S rows are private to this m-group; sync only its 2 warps
        asm volatile("bar.sync %0, 64;" :: "r"(1 + mgrp));

        // ---- O += S V ----  (V^T: keys 2t,2t+1 adjacent -> LDS.64 B-frags)
#pragma unroll
        for (int ks = 0; ks < 8; ks++) {
            float2 s0 = *reinterpret_cast<const float2*>(&sK[(m0 + g) * 72 + ks * 8 + 2 * t]);
            float2 s1 = *reinterpret_cast<const float2*>(&sK[(m0 + g + 8) * 72 + ks * 8 + 2 * t]);
            float a[4] = {s0.x, s1.x, s0.y, s1.y};
#pragma unroll
            for (int j = 0; j < 4; j++) {
                float2 vb = *reinterpret_cast<const float2*>(
                    &sV[(n0 + 8 * j + g) * 72 + ks * 8 + 2 * t]);
                float bb[2] = {vb.x, vb.y};
                mma8(o[j], a, bb);
            }
        }

        if (ii + 1 < nkt) { cpa_wait0(); __syncthreads(); }
    }

    // accumulate into g_attn
#pragma unroll
    for (int j = 0; j < 4; j++) {
        int col = head * 64 + n0 + 8 * j + 2 * t;
        float* p0 = &attn[(size_t)(base + q0 + m0 + g) * 256 + col];
        float* p1 = &attn[(size_t)(base + q0 + m0 + g + 8) * 256 + col];
        atomicAdd(p0, o[j][0]);
        atomicAdd(p0 + 1, o[j][1]);
        atomicAdd(p1, o[j][2]);
        atomicAdd(p1 + 1, o[j][3]);
    }
}

// ---------------------------------------------------------------------------
// o_in = tf32r(u * ln(attn)), warp-per-row
// ---------------------------------------------------------------------------
__global__ __launch_bounds__(256) void ln_u_kernel(const float* __restrict__ attn,
                                                   const float* __restrict__ h,
                                                   float* __restrict__ oin) {
    int row = blockIdx.x * 8 + (threadIdx.x >> 5);
    int lane = threadIdx.x & 31;
    const float* r = attn + (size_t)row * 256;
    float4 v[2];
    float s = 0.f, q = 0.f;
#pragma unroll
    for (int i = 0; i < 2; i++) {
        v[i] = *reinterpret_cast<const float4*>(&r[lane * 4 + i * 128]);
        s += v[i].x + v[i].y + v[i].z + v[i].w;
        q += v[i].x * v[i].x + v[i].y * v[i].y + v[i].z * v[i].z + v[i].w * v[i].w;
    }
#pragma unroll
    for (int o = 16; o > 0; o >>= 1) {
        s += __shfl_xor_sync(0xffffffffu, s, o);
        q += __shfl_xor_sync(0xffffffffu, q, o);
    }
    float m = s * (1.f / 256.f);
    float rstd = rsqrtf(q * (1.f / 256.f) - m * m + 1e-6f);
    float* ov = oin + (size_t)row * 256;
#pragma unroll
    for (int i = 0; i < 2; i++) {
        float4 u4 = *reinterpret_cast<const float4*>(
            &h[(size_t)row * 1024 + lane * 4 + i * 128]);
        float4 w;
        w.x = tf32r(u4.x * (v[i].x - m) * rstd);
        w.y = tf32r(u4.y * (v[i].y - m) * rstd);
        w.z = tf32r(u4.z * (v[i].z - m) * rstd);
        w.w = tf32r(u4.w * (v[i].w - m) * rstd);
        *reinterpret_cast<float4*>(&ov[lane * 4 + i * 128]) = w;
    }
}

// ---------------------------------------------------------------------------
// out = o_in @ o_w^T + o_b + x   tf32 MMA, 128x64 tile, BK=32, cp.async
// double buffer, k-relabel LDS.64 fragments. W pre-rounded (g_owr, [n][k]).
// ---------------------------------------------------------------------------
#define G2_SMEM (18432 * 4)

__global__ __launch_bounds__(256) void gemm_out_kernel(const float* __restrict__ A,
                                                       const float* __restrict__ Wr,
                                                       const float* __restrict__ bias,
                                                       const float* __restrict__ x,
                                                       float* __restrict__ out) {
    extern __shared__ float sm[];
    float* sA = sm;            // [2][128][36]
    float* sB = sm + 9216;     // [2][64][72]  W[n][k]
    int bm = blockIdx.y * 128, bn = blockIdx.x * 64;
    int tid = threadIdx.x, lane = tid & 31, wid = tid >> 5;
    int g = lane >> 2, t = lane & 3;
    int wm = (wid >> 1) * 32, wn = (wid & 1) * 32;

    auto pf = [&](int k0, int buf) {
        float* dA = sA + buf * 4608;
        float* dB = sB + buf * 4608;
#pragma unroll
        for (int p = 0; p < 4; p++) {
            int idx = tid + p * 256;
            int row = idx >> 3, f4 = (idx & 7) << 2;
            cpa16(&dA[row * 36 + f4], &A[(size_t)(bm + row) * 256 + k0 + f4]);
        }
#pragma unroll
        for (int p = 0; p < 2; p++) {
            int idx = tid + p * 256;
            int row = idx >> 3, f4 = (idx & 7) << 2;
            cpa16(&dB[row * 72 + f4], &Wr[(size_t)(bn + row) * 256 + k0 + f4]);
        }
        cpa_commit();
    };

    float acc[2][4][4] = {};
    pf(0, 0);
    for (int it = 0; it < 8; it++) {
        cpa_wait0();
        __syncthreads();
        if (it + 1 < 8) pf((it + 1) * 32, (it + 1) & 1);
        float* cA = sA + (it & 1) * 4608;
        float* cB = sB + (it & 1) * 4608;
#pragma unroll
        for (int kk = 0; kk < 32; kk += 8) {
            float a[2][4], bb[4][2];
#pragma unroll
            for (int i = 0; i < 2; i++) {
                int r = wm + 16 * i + g;
                float2 f0 = *reinterpret_cast<const float2*>(&cA[r * 36 + kk + 2 * t]);
                float2 f1 = *reinterpret_cast<const float2*>(&cA[(r + 8) * 36 + kk + 2 * t]);
                a[i][0] = f0.x; a[i][1] = f1.x; a[i][2] = f0.y; a[i][3] = f1.y;
            }
#pragma unroll
            for (int j = 0; j < 4; j++) {
                float2 fb = *reinterpret_cast<const float2*>(
                    &cB[(wn + 8 * j + g) * 72 + kk + 2 * t]);
                bb[j][0] = fb.x; bb[j][1] = fb.y;
            }
#pragma unroll
            for (int i = 0; i < 2; i++)
#pragma unroll
                for (int j = 0; j < 4; j++) mma8(acc[i][j], a[i], bb[j]);
        }
        __syncthreads();
    }
#pragma unroll
    for (int i = 0; i < 2; i++) {
        int r = bm + wm + 16 * i + g;
#pragma unroll
        for (int j = 0; j < 4; j++) {
            int c = bn + wn + 8 * j + 2 * t;
            float2 b2 = *reinterpret_cast<const float2*>(&bias[c]);
            float2 x0 = *reinterpret_cast<const float2*>(&x[(size_t)r * Dm + c]);
            float2 x1 = *reinterpret_cast<const float2*>(&x[(size_t)(r + 8) * Dm + c]);
            float* s = acc[i][j];
            *reinterpret_cast<float2*>(&out[(size_t)r * Dm + c]) =
                make_float2(s[0] + b2.x + x0.x, s[1] + b2.y + x0.y);
            *reinterpret_cast<float2*>(&out[(size_t)(r + 8) * Dm + c]) =
                make_float2(s[2] + b2.x + x1.x, s[3] + b2.y + x1.y);
        }
    }
}

// ---------------------------------------------------------------------------
extern "C" void kernel_launch(void* const* d_in, const int* in_sizes, int n_in,
                              void* d_out, int out_size) {
    const float* x    = (const float*)d_in[0];
    const float* uvqk = (const float*)d_in[1];
    const float* o_w  = (const float*)d_in[2];
    const float* o_b  = (const float*)d_in[3];
    const float* ts_w = (const float*)d_in[4];
    const int*   ts   = (const int*)d_in[5];
    float* out = (float*)d_out;

    float *xn, *uvqkrT, *owr, *h, *vT, *attn, *oin;
    cudaGetSymbolAddress((void**)&xn,     g_xn);
    cudaGetSymbolAddress((void**)&uvqkrT, g_uvqkrT);
    cudaGetSymbolAddress((void**)&owr,    g_owr);
    cudaGetSymbolAddress((void**)&h,      g_h);
    cudaGetSymbolAddress((void**)&vT,     g_vT);
    cudaGetSymbolAddress((void**)&attn,   g_attn);
    cudaGetSymbolAddress((void**)&oin,    g_oin);

    cudaFuncSetAttribute(attn_kernel, cudaFuncAttributeMaxDynamicSharedMemorySize,
                         ATTN_SMEM);
    cudaFuncSetAttribute(gemm_silu_kernel, cudaFuncAttributeMaxDynamicSharedMemorySize,
                         G1_SMEM);
    cudaFuncSetAttribute(gemm_out_kernel, cudaFuncAttributeMaxDynamicSharedMemorySize,
                         G2_SMEM);

    cudaMemsetAsync(attn, 0, (size_t)T_ * 256 * sizeof(float));
    ln_x_kernel<<<800, 256>>>(x, xn);
    cvtT_kernel<<<dim3(32, 16), 256>>>(uvqk, uvqkrT);
    cvt_tf32_kernel<<<128, 256>>>((const float4*)o_w, (float4*)owr);
    gemm_silu_kernel<<<dim3(16, 50), 256, G1_SMEM>>>(xn, uvqkrT, h, vT);
    attn_kernel<<<dim3(216, 4), 256, ATTN_SMEM>>>(h, vT, ts, ts_w, attn);
    ln_u_kernel<<<800, 256>>>(attn, h, oin);
    gemm_out_kernel<<<dim3(8, 50), 256, G2_SMEM>>>(oin, owr, o_b, x, out);
}